// round 4
// baseline (speedup 1.0000x reference)
#include <cuda_runtime.h>
#include <cuda_bf16.h>
#include <math_constants.h>
#include <cstdint>

// Problem constants (fixed by the dataset)
#define BATCH   32
#define SEQ     512
#define DMODEL  512
#define HEADS   8
#define DKH     64
#define MROWS   (BATCH * SEQ)          // 16384

// ---------------------------------------------------------------------------
// Scratch (allocation-free rule: __device__ globals)
// ---------------------------------------------------------------------------
__device__ float g_Qp[MROWS * DMODEL];
__device__ float g_Kp[MROWS * DMODEL];
__device__ float g_Vp[MROWS * DMODEL];
__device__ __nv_bfloat16 g_Ahi[MROWS * DMODEL];
__device__ __nv_bfloat16 g_Alo[MROWS * DMODEL];
__device__ __nv_bfloat16 g_Wthi[DMODEL * DMODEL];
__device__ __nv_bfloat16 g_Wtlo[DMODEL * DMODEL];

// f32x2 packed-FMA helpers (Blackwell FFMA2; exact IEEE fp32 per lane)
#define FMA2(acc, a, b)                                                      \
    asm("fma.rn.f32x2 %0, %1, %2, %0;" : "+l"(acc) : "l"(a), "l"(b))
#define SPLAT2(dst, fu)                                                      \
    asm("mov.b64 %0, {%1,%1};" : "=l"(dst) : "r"(fu))
#define UNPK2(lo, hi, src)                                                   \
    asm("mov.b64 {%0,%1}, %2;" : "=r"(lo), "=r"(hi) : "l"(src))

// ---------------------------------------------------------------------------
// Split fp32 activations into hi/lo bf16 (2-term split).
// ---------------------------------------------------------------------------
__global__ void __launch_bounds__(256)
convA(const float4* __restrict__ X, uint2* __restrict__ Hi,
      uint2* __restrict__ Lo, int n4)
{
    int i = blockIdx.x * 256 + threadIdx.x;
    if (i >= n4) return;
    float4 x = X[i];
    __nv_bfloat16 h0 = __float2bfloat16(x.x);
    __nv_bfloat16 h1 = __float2bfloat16(x.y);
    __nv_bfloat16 h2 = __float2bfloat16(x.z);
    __nv_bfloat16 h3 = __float2bfloat16(x.w);
    __nv_bfloat16 l0 = __float2bfloat16(x.x - __bfloat162float(h0));
    __nv_bfloat16 l1 = __float2bfloat16(x.y - __bfloat162float(h1));
    __nv_bfloat16 l2 = __float2bfloat16(x.z - __bfloat162float(h2));
    __nv_bfloat16 l3 = __float2bfloat16(x.w - __bfloat162float(h3));
    uint2 uh, ul;
    uh.x = ((uint32_t)__bfloat16_as_ushort(h1) << 16) | __bfloat16_as_ushort(h0);
    uh.y = ((uint32_t)__bfloat16_as_ushort(h3) << 16) | __bfloat16_as_ushort(h2);
    ul.x = ((uint32_t)__bfloat16_as_ushort(l1) << 16) | __bfloat16_as_ushort(l0);
    ul.y = ((uint32_t)__bfloat16_as_ushort(l3) << 16) | __bfloat16_as_ushort(l2);
    Hi[i] = uh;
    Lo[i] = ul;
}

// ---------------------------------------------------------------------------
// Transpose + split weights: Wt[n][k] = W[k][n] (hi/lo bf16).
// ---------------------------------------------------------------------------
__global__ void __launch_bounds__(256)
convT(const float* __restrict__ W, __nv_bfloat16* __restrict__ Thi,
      __nv_bfloat16* __restrict__ Tlo)
{
    __shared__ float s[32][33];
    const int bx = blockIdx.x, by = blockIdx.y;
    const int tx = threadIdx.x, ty = threadIdx.y;
#pragma unroll
    for (int i = 0; i < 32; i += 8)
        s[ty + i][tx] = W[(by * 32 + ty + i) * DMODEL + bx * 32 + tx];
    __syncthreads();
#pragma unroll
    for (int i = 0; i < 32; i += 8) {
        float x = s[tx][ty + i];
        int n = bx * 32 + ty + i;
        int k = by * 32 + tx;
        __nv_bfloat16 h = __float2bfloat16(x);
        Thi[n * DMODEL + k] = h;
        Tlo[n * DMODEL + k] = __float2bfloat16(x - __bfloat162float(h));
    }
}

// ---------------------------------------------------------------------------
// fp32 SGEMM with packed f32x2 FMA. gridDim.z selects (A,W,bias,C) pair,
// so Q and K projections run as ONE launch (tail amortization).
// ---------------------------------------------------------------------------
__global__ void __launch_bounds__(256, 2)
sgemm_bias_x2_qk(const float* __restrict__ A0, const float* __restrict__ W0,
                 const float* __restrict__ bias0, float* __restrict__ C0,
                 const float* __restrict__ A1, const float* __restrict__ W1,
                 const float* __restrict__ bias1, float* __restrict__ C1)
{
    __shared__ float As[8][128];   // transposed A tile: As[k][m]
    __shared__ float Bs[8][128];   // Bs[k][n]

    const float* A    = blockIdx.z ? A1 : A0;
    const float* W    = blockIdx.z ? W1 : W0;
    const float* bias = blockIdx.z ? bias1 : bias0;
    float*       C    = blockIdx.z ? C1 : C0;

    const int tid = threadIdx.x;
    const int bm = blockIdx.y * 128;
    const int bn = blockIdx.x * 128;
    const int tx = tid & 15;
    const int ty = tid >> 4;

    const int arow = tid >> 1;
    const int ac4  = (tid & 1) << 2;
    const int brow = tid >> 5;
    const int bc4  = (tid & 31) << 2;

    const float* Ap = A + (size_t)(bm + arow) * DMODEL + ac4;
    const float* Wp = W + (size_t)brow * DMODEL + (bn + bc4);

    unsigned long long acc2[8][4];
#pragma unroll
    for (int i = 0; i < 8; i++)
#pragma unroll
        for (int j = 0; j < 4; j++) acc2[i][j] = 0ull;

    for (int k0 = 0; k0 < DMODEL; k0 += 8) {
        const float4 av = *(const float4*)(Ap + k0);
        const float4 bv = *(const float4*)(Wp + (size_t)k0 * DMODEL);
        __syncthreads();
        As[ac4 + 0][arow] = av.x;
        As[ac4 + 1][arow] = av.y;
        As[ac4 + 2][arow] = av.z;
        As[ac4 + 3][arow] = av.w;
        *(float4*)&Bs[brow][bc4] = bv;
        __syncthreads();

#pragma unroll
        for (int k = 0; k < 8; k++) {
            float a[8];
            *(float4*)&a[0] = *(const float4*)&As[k][ty * 8];
            *(float4*)&a[4] = *(const float4*)&As[k][ty * 8 + 4];
            const ulonglong2 tb0 = *(const ulonglong2*)&Bs[k][tx * 8];
            const ulonglong2 tb1 = *(const ulonglong2*)&Bs[k][tx * 8 + 4];
            unsigned long long b2[4];
            b2[0] = tb0.x; b2[1] = tb0.y; b2[2] = tb1.x; b2[3] = tb1.y;
            unsigned long long a2[8];
#pragma unroll
            for (int i = 0; i < 8; i++) SPLAT2(a2[i], __float_as_uint(a[i]));
#pragma unroll
            for (int i = 0; i < 8; i++)
#pragma unroll
                for (int j = 0; j < 4; j++)
                    FMA2(acc2[i][j], a2[i], b2[j]);
        }
    }

#pragma unroll
    for (int i = 0; i < 8; i++) {
        float* crow = C + (size_t)(bm + ty * 8 + i) * DMODEL + bn + tx * 8;
        const float* brw = bias + bn + tx * 8;
#pragma unroll
        for (int jp = 0; jp < 4; jp++) {
            unsigned lo, hi;
            UNPK2(lo, hi, acc2[i][jp]);
            float2 o;
            o.x = __uint_as_float(lo) + brw[jp * 2];
            o.y = __uint_as_float(hi) + brw[jp * 2 + 1];
            *(float2*)(crow + jp * 2) = o;
        }
    }
}

// ---------------------------------------------------------------------------
// Tensor-core GEMM (bf16 3-MMA split) — V and output projections.
// ---------------------------------------------------------------------------
#define GBM 128
#define GBN 128
#define GBK 32
#define GSTR 40
#define GSTAGE 20480
#define GNK (DMODEL / GBK)

#define MMA16816(c, a, b0, b1)                                               \
    asm volatile(                                                            \
        "mma.sync.aligned.m16n8k16.row.col.f32.bf16.bf16.f32 "               \
        "{%0,%1,%2,%3},{%4,%5,%6,%7},{%8,%9},{%0,%1,%2,%3};"                 \
        : "+f"(c[0]), "+f"(c[1]), "+f"(c[2]), "+f"(c[3])                     \
        : "r"(a[0]), "r"(a[1]), "r"(a[2]), "r"(a[3]), "r"(b0), "r"(b1))

#define CPA16(sdst, gsrc)                                                    \
    {                                                                        \
        uint32_t _d = (uint32_t)__cvta_generic_to_shared(sdst);              \
        asm volatile("cp.async.cg.shared.global [%0], [%1], 16;"             \
                     :: "r"(_d), "l"(gsrc));                                 \
    }

__global__ void __launch_bounds__(256, 2)
gemm_bf16x3(const __nv_bfloat16* __restrict__ Ahi,
            const __nv_bfloat16* __restrict__ Alo,
            const __nv_bfloat16* __restrict__ Bthi,
            const __nv_bfloat16* __restrict__ Btlo,
            const float* __restrict__ bias, float* __restrict__ C)
{
    extern __shared__ __nv_bfloat16 sm[];
    const int tid = threadIdx.x;
    const int lane = tid & 31;
    const int g = lane >> 2;
    const int tg = lane & 3;
    const int wid = tid >> 5;
    const int warp_m = wid >> 1;
    const int warp_n = wid & 1;
    const int bm = blockIdx.y * GBM;
    const int bn = blockIdx.x * GBN;

    float acc[2][8][4];
#pragma unroll
    for (int mt = 0; mt < 2; mt++)
#pragma unroll
        for (int nt = 0; nt < 8; nt++)
#pragma unroll
            for (int j = 0; j < 4; j++) acc[mt][nt][j] = 0.0f;

    const int ld_row = tid >> 2;
    const int ld_q   = tid & 3;

    const __nv_bfloat16* gAh = Ahi + (size_t)bm * DMODEL;
    const __nv_bfloat16* gAl = Alo + (size_t)bm * DMODEL;
    const __nv_bfloat16* gBh = Bthi + (size_t)bn * DMODEL;
    const __nv_bfloat16* gBl = Btlo + (size_t)bn * DMODEL;

    auto issue_stage = [&](int kt) {
        const int k0 = kt * GBK;
        __nv_bfloat16* base = sm + (kt & 1) * GSTAGE;
#pragma unroll
        for (int cc = 0; cc < 2; cc++) {
            const int row = ld_row + cc * 64;
            const int soff = row * GSTR + ld_q * 8;
            const size_t goff = (size_t)row * DMODEL + k0 + ld_q * 8;
            CPA16(base + soff,         gAh + goff);
            CPA16(base + 5120 + soff,  gAl + goff);
            CPA16(base + 10240 + soff, gBh + goff);
            CPA16(base + 15360 + soff, gBl + goff);
        }
        asm volatile("cp.async.commit_group;");
    };

    issue_stage(0);

    for (int kt = 0; kt < GNK; kt++) {
        asm volatile("cp.async.wait_group 0;" ::: "memory");
        __syncthreads();
        if (kt + 1 < GNK) issue_stage(kt + 1);

        const __nv_bfloat16* sa_hi = sm + (kt & 1) * GSTAGE;
        const __nv_bfloat16* sa_lo = sa_hi + 5120;
        const __nv_bfloat16* sb_hi = sa_hi + 10240;
        const __nv_bfloat16* sb_lo = sa_hi + 15360;

#pragma unroll
        for (int ks = 0; ks < 2; ks++) {
            const int kb = ks * 16 + tg * 2;
            uint32_t ah[2][4], al[2][4];
#pragma unroll
            for (int mt = 0; mt < 2; mt++) {
                const int r = warp_m * 32 + mt * 16 + g;
                const __nv_bfloat16* pa = sa_hi + r * GSTR + kb;
                ah[mt][0] = *(const uint32_t*)(pa);
                ah[mt][1] = *(const uint32_t*)(pa + 8 * GSTR);
                ah[mt][2] = *(const uint32_t*)(pa + 8);
                ah[mt][3] = *(const uint32_t*)(pa + 8 * GSTR + 8);
                const __nv_bfloat16* pl = sa_lo + r * GSTR + kb;
                al[mt][0] = *(const uint32_t*)(pl);
                al[mt][1] = *(const uint32_t*)(pl + 8 * GSTR);
                al[mt][2] = *(const uint32_t*)(pl + 8);
                al[mt][3] = *(const uint32_t*)(pl + 8 * GSTR + 8);
            }
#pragma unroll
            for (int nt = 0; nt < 8; nt++) {
                const int n = warp_n * 64 + nt * 8 + g;
                const __nv_bfloat16* pb = sb_hi + n * GSTR + kb;
                uint32_t bh0 = *(const uint32_t*)(pb);
                uint32_t bh1 = *(const uint32_t*)(pb + 8);
                const __nv_bfloat16* pbl = sb_lo + n * GSTR + kb;
                uint32_t bl0 = *(const uint32_t*)(pbl);
                uint32_t bl1 = *(const uint32_t*)(pbl + 8);
#pragma unroll
                for (int mt = 0; mt < 2; mt++) {
                    MMA16816(acc[mt][nt], ah[mt], bh0, bh1);
                    MMA16816(acc[mt][nt], ah[mt], bl0, bl1);
                    MMA16816(acc[mt][nt], al[mt], bh0, bh1);
                }
            }
        }
    }

#pragma unroll
    for (int mt = 0; mt < 2; mt++) {
        const int r0 = bm + warp_m * 32 + mt * 16 + g;
#pragma unroll
        for (int nt = 0; nt < 8; nt++) {
            const int col = bn + warp_n * 64 + nt * 8 + tg * 2;
            const float bx = bias[col];
            const float by = bias[col + 1];
            float2 v0 = make_float2(acc[mt][nt][0] + bx, acc[mt][nt][1] + by);
            float2 v1 = make_float2(acc[mt][nt][2] + bx, acc[mt][nt][3] + by);
            *(float2*)&C[(size_t)r0 * DMODEL + col] = v0;
            *(float2*)&C[(size_t)(r0 + 8) * DMODEL + col] = v1;
        }
    }
}

// ---------------------------------------------------------------------------
// Sparse causal attention with top-k renormalization.
// f32x2 packed score accumulation; occ 2 (NO reg cap -> no spills).
// Epilogue writes the bf16 hi/lo split of the head-concat output directly
// (feeds gemm_bf16x3 for the output projection; saves a pass + convA).
// ---------------------------------------------------------------------------
#define AT_ROWS 16
#define KTILE   128
#define KPAD    (KTILE + 4)
#define CAP     32
#define NEGINF  (-CUDART_INF_F)

__global__ void __launch_bounds__(256, 2)
attn_sparse(const float* __restrict__ Q, const float* __restrict__ K,
            const float* __restrict__ V, const int* __restrict__ kidx_p,
            __nv_bfloat16* __restrict__ Ohi, __nv_bfloat16* __restrict__ Olo)
{
    __shared__ float ks[DKH][KPAD];        // transposed K tile
    __shared__ float qs[AT_ROWS][DKH];
    __shared__ float lw[AT_ROWS][CAP];
    __shared__ int   lj[AT_ROWS][CAP];
    __shared__ int   lcnt[AT_ROWS];

    const int bh = blockIdx.y;
    const int b  = bh >> 3;
    const int h  = bh & 7;
    const int row_base = blockIdx.x * AT_ROWS;
    const int tid  = threadIdx.x;
    const int wid  = tid >> 5;
    const int lane = tid & 31;
    const int kk   = *kidx_p;

    const size_t base = ((size_t)b * SEQ) * DMODEL + (size_t)h * DKH;

    for (int i = tid; i < AT_ROWS * DKH; i += 256) {
        int rr = i >> 6, d = i & 63;
        qs[rr][d] = Q[base + (size_t)(row_base + rr) * DMODEL + d];
    }

    const int nkeys = row_base + AT_ROWS - 1;   // strictly-causal: keys j < r
    const int lr0 = wid * 2;

    unsigned long long sc2[2][8];
#pragma unroll
    for (int p = 0; p < 8; p++) { sc2[0][p] = 0ull; sc2[1][p] = 0ull; }

    // ---- score pass: QK^T over key tiles ----
#pragma unroll
    for (int tt = 0; tt < 4; tt++) {
        const int t0 = tt << 7;
        if (t0 >= nkeys) break;
        const int tl = min(KTILE, nkeys - t0);
        __syncthreads();
        for (int i = tid; i < KTILE * 16; i += 256) {
            const int key = i >> 4;
            const int d4  = (i & 15) << 2;
            float4 kv;
            if (key < tl)
                kv = *(const float4*)&K[base + (size_t)(t0 + key) * DMODEL + d4];
            else
                kv = make_float4(0.f, 0.f, 0.f, 0.f);
            ks[d4 + 0][key] = kv.x;
            ks[d4 + 1][key] = kv.y;
            ks[d4 + 2][key] = kv.z;
            ks[d4 + 3][key] = kv.w;
        }
        __syncthreads();
#pragma unroll 4
        for (int d4 = 0; d4 < DKH; d4 += 4) {
            const float4 qa4 = *(const float4*)&qs[lr0][d4];
            const float4 qb4 = *(const float4*)&qs[lr0 + 1][d4];
#pragma unroll
            for (int dd = 0; dd < 4; dd++) {
                const ulonglong2 kv2 =
                    *(const ulonglong2*)&ks[d4 + dd][lane << 2];
                unsigned long long qa2, qb2;
                SPLAT2(qa2, __float_as_uint((&qa4.x)[dd]));
                SPLAT2(qb2, __float_as_uint((&qb4.x)[dd]));
                FMA2(sc2[0][tt * 2 + 0], qa2, kv2.x);
                FMA2(sc2[0][tt * 2 + 1], qa2, kv2.y);
                FMA2(sc2[1][tt * 2 + 0], qb2, kv2.x);
                FMA2(sc2[1][tt * 2 + 1], qb2, kv2.y);
            }
        }
    }

    // unpack packed accumulators into scalar score slots
    float sc[2][16];
#pragma unroll
    for (int rr = 0; rr < 2; rr++)
#pragma unroll
        for (int p = 0; p < 8; p++) {
            unsigned lo, hi;
            UNPK2(lo, hi, sc2[rr][p]);
            sc[rr][p * 2]     = __uint_as_float(lo);
            sc[rr][p * 2 + 1] = __uint_as_float(hi);
        }

    // ---- mask invalid keys & apply 1/sqrt(DK) ----
#pragma unroll
    for (int rr = 0; rr < 2; rr++) {
        const int r = row_base + lr0 + rr;
#pragma unroll
        for (int s = 0; s < 16; s++) {
            const int j = ((s >> 2) << 7) + (lane << 2) + (s & 3);
            sc[rr][s] = (j < r) ? sc[rr][s] * 0.125f : NEGINF;
        }
    }

    // ---- per-row: top-k threshold, weights, sparse PV ----
#pragma unroll
    for (int rr = 0; rr < 2; rr++) {
        const int r  = row_base + lr0 + rr;
        const int lr = lr0 + rr;
        float o0 = 0.0f, o1 = 0.0f;

        if (r > 0) {
            float tmp[16];
#pragma unroll
            for (int s = 0; s < 16; s++) tmp[s] = sc[rr][s];

            const int nex = (r >= kk) ? kk : 1;
            float m = 0.0f, t = NEGINF;
            for (int e = 0; e < nex; e++) {
                float lm = NEGINF;
#pragma unroll
                for (int s = 0; s < 16; s++) lm = fmaxf(lm, tmp[s]);
                float wm = lm;
#pragma unroll
                for (int off = 16; off > 0; off >>= 1)
                    wm = fmaxf(wm, __shfl_xor_sync(0xffffffffu, wm, off));
                if (e == 0) m = wm;
                t = wm;
                const unsigned ball = __ballot_sync(0xffffffffu, lm == wm);
                const int owner = __ffs(ball) - 1;
                if (lane == owner) {
                    bool rm = false;
#pragma unroll
                    for (int s = 0; s < 16; s++) {
                        if (!rm && tmp[s] == wm) { tmp[s] = NEGINF; rm = true; }
                    }
                }
            }
            if (r < kk) t = -3.0e38f;   // dense softmax path: keep all valid

            float ksum = 0.0f;
#pragma unroll
            for (int s = 0; s < 16; s++)
                if (sc[rr][s] >= t) ksum += __expf(sc[rr][s] - m);
#pragma unroll
            for (int off = 16; off > 0; off >>= 1)
                ksum += __shfl_xor_sync(0xffffffffu, ksum, off);
            const float inv = 1.0f / ksum;

            if (lane == 0) lcnt[lr] = 0;
            __syncwarp();
#pragma unroll
            for (int s = 0; s < 16; s++) {
                if (sc[rr][s] >= t) {
                    const int p = atomicAdd(&lcnt[lr], 1);
                    if (p < CAP) {
                        lw[lr][p] = __expf(sc[rr][s] - m) * inv;
                        lj[lr][p] = ((s >> 2) << 7) + (lane << 2) + (s & 3);
                    }
                }
            }
            __syncwarp();
            const int cnt = min(lcnt[lr], CAP);
            for (int e = 0; e < cnt; e++) {
                const float w = lw[lr][e];
                const int   j = lj[lr][e];
                const float* vrow = &V[base + (size_t)j * DMODEL];
                o0 = fmaf(w, vrow[lane], o0);
                o1 = fmaf(w, vrow[lane + 32], o1);
            }
            __syncwarp();
        }
        // fused bf16 hi/lo split of the head-concat output
        const size_t p0 = base + (size_t)r * DMODEL + lane;
        const __nv_bfloat16 h0 = __float2bfloat16(o0);
        const __nv_bfloat16 h1 = __float2bfloat16(o1);
        Ohi[p0]      = h0;
        Ohi[p0 + 32] = h1;
        Olo[p0]      = __float2bfloat16(o0 - __bfloat162float(h0));
        Olo[p0 + 32] = __float2bfloat16(o1 - __bfloat162float(h1));
    }
}

// ---------------------------------------------------------------------------
extern "C" void kernel_launch(void* const* d_in, const int* in_sizes, int n_in,
                              void* d_out, int out_size)
{
    const float* q   = (const float*)d_in[0];
    const float* k   = (const float*)d_in[1];
    const float* v   = (const float*)d_in[2];
    const float* w_q = (const float*)d_in[3];
    const float* b_q = (const float*)d_in[4];
    const float* w_k = (const float*)d_in[5];
    const float* b_k = (const float*)d_in[6];
    const float* w_v = (const float*)d_in[7];
    const float* b_v = (const float*)d_in[8];
    const float* w_o = (const float*)d_in[9];
    const float* b_o = (const float*)d_in[10];
    const int*   kid = (const int*)d_in[11];
    float* out = (float*)d_out;

    float *Qp, *Kp, *Vp;
    __nv_bfloat16 *Ahi, *Alo, *Wthi, *Wtlo;
    cudaGetSymbolAddress((void**)&Qp, g_Qp);
    cudaGetSymbolAddress((void**)&Kp, g_Kp);
    cudaGetSymbolAddress((void**)&Vp, g_Vp);
    cudaGetSymbolAddress((void**)&Ahi, g_Ahi);
    cudaGetSymbolAddress((void**)&Alo, g_Alo);
    cudaGetSymbolAddress((void**)&Wthi, g_Wthi);
    cudaGetSymbolAddress((void**)&Wtlo, g_Wtlo);

    cudaFuncSetAttribute(gemm_bf16x3,
                         cudaFuncAttributeMaxDynamicSharedMemorySize,
                         2 * GSTAGE * (int)sizeof(__nv_bfloat16));

    const int n4 = MROWS * DMODEL / 4;
    const int cblk = (n4 + 255) / 256;
    dim3 tgrid(16, 16), tblk(32, 8);
    dim3 ggrid(DMODEL / GBN, MROWS / GBM);        // (4, 128)
    dim3 ggrid_qk(DMODEL / 128, MROWS / 128, 2);  // Q and K in one launch
    const int smem = 2 * GSTAGE * (int)sizeof(__nv_bfloat16);

    // V projection path first (independent of Q/K).
    convT<<<tgrid, tblk>>>(w_v, Wthi, Wtlo);
    convA<<<cblk, 256>>>((const float4*)v, (uint2*)Ahi, (uint2*)Alo, n4);
    gemm_bf16x3<<<ggrid, 256, smem>>>(Ahi, Alo, Wthi, Wtlo, b_v, Vp);

    // Q + K projections: exact fp32 (packed f32x2 FMA), one launch.
    sgemm_bias_x2_qk<<<ggrid_qk, 256>>>(q, w_q, b_q, Qp, k, w_k, b_k, Kp);

    // Pre-split the output-projection weights before attention (independent),
    // so the final GEMM starts immediately after attn completes.
    convT<<<tgrid, tblk>>>(w_o, Wthi, Wtlo);

    // Attention — writes bf16 hi/lo split directly into Ahi/Alo.
    dim3 ga(SEQ / AT_ROWS, BATCH * HEADS); // (32, 256)
    attn_sparse<<<ga, 256>>>(Qp, Kp, Vp, kid, Ahi, Alo);

    // Output projection.
    gemm_bf16x3<<<ggrid, 256, smem>>>(Ahi, Alo, Wthi, Wtlo, b_o, out);
}

// round 5
// speedup vs baseline: 1.0898x; 1.0898x over previous
#include <cuda_runtime.h>
#include <cuda_bf16.h>
#include <math_constants.h>
#include <cstdint>

// Problem constants (fixed by the dataset)
#define BATCH   32
#define SEQ     512
#define DMODEL  512
#define HEADS   8
#define DKH     64
#define MROWS   (BATCH * SEQ)          // 16384

// ---------------------------------------------------------------------------
// Scratch (allocation-free rule: __device__ globals)
// ---------------------------------------------------------------------------
__device__ float g_Qp[MROWS * DMODEL];
__device__ float g_Kp[MROWS * DMODEL];
__device__ float g_Vp[MROWS * DMODEL];
__device__ float g_AO[MROWS * DMODEL];
__device__ __nv_bfloat16 g_Ahi[MROWS * DMODEL];
__device__ __nv_bfloat16 g_Alo[MROWS * DMODEL];
__device__ __nv_bfloat16 g_Wthi[DMODEL * DMODEL];
__device__ __nv_bfloat16 g_Wtlo[DMODEL * DMODEL];

// f32x2 packed-FMA helpers (Blackwell FFMA2; exact IEEE fp32 per lane)
#define FMA2(acc, a, b)                                                      \
    asm("fma.rn.f32x2 %0, %1, %2, %0;" : "+l"(acc) : "l"(a), "l"(b))
#define SPLAT2(dst, fu)                                                      \
    asm("mov.b64 %0, {%1,%1};" : "=l"(dst) : "r"(fu))
#define UNPK2(lo, hi, src)                                                   \
    asm("mov.b64 {%0,%1}, %2;" : "=r"(lo), "=r"(hi) : "l"(src))

// ---------------------------------------------------------------------------
// Split fp32 activations into hi/lo bf16 (2-term split).
// ---------------------------------------------------------------------------
__global__ void __launch_bounds__(256)
convA(const float4* __restrict__ X, uint2* __restrict__ Hi,
      uint2* __restrict__ Lo, int n4)
{
    int i = blockIdx.x * 256 + threadIdx.x;
    if (i >= n4) return;
    float4 x = X[i];
    __nv_bfloat16 h0 = __float2bfloat16(x.x);
    __nv_bfloat16 h1 = __float2bfloat16(x.y);
    __nv_bfloat16 h2 = __float2bfloat16(x.z);
    __nv_bfloat16 h3 = __float2bfloat16(x.w);
    __nv_bfloat16 l0 = __float2bfloat16(x.x - __bfloat162float(h0));
    __nv_bfloat16 l1 = __float2bfloat16(x.y - __bfloat162float(h1));
    __nv_bfloat16 l2 = __float2bfloat16(x.z - __bfloat162float(h2));
    __nv_bfloat16 l3 = __float2bfloat16(x.w - __bfloat162float(h3));
    uint2 uh, ul;
    uh.x = ((uint32_t)__bfloat16_as_ushort(h1) << 16) | __bfloat16_as_ushort(h0);
    uh.y = ((uint32_t)__bfloat16_as_ushort(h3) << 16) | __bfloat16_as_ushort(h2);
    ul.x = ((uint32_t)__bfloat16_as_ushort(l1) << 16) | __bfloat16_as_ushort(l0);
    ul.y = ((uint32_t)__bfloat16_as_ushort(l3) << 16) | __bfloat16_as_ushort(l2);
    Hi[i] = uh;
    Lo[i] = ul;
}

// ---------------------------------------------------------------------------
// Transpose + split weights: Wt[n][k] = W[k][n] (hi/lo bf16).
// ---------------------------------------------------------------------------
__global__ void __launch_bounds__(256)
convT(const float* __restrict__ W, __nv_bfloat16* __restrict__ Thi,
      __nv_bfloat16* __restrict__ Tlo)
{
    __shared__ float s[32][33];
    const int bx = blockIdx.x, by = blockIdx.y;
    const int tx = threadIdx.x, ty = threadIdx.y;
#pragma unroll
    for (int i = 0; i < 32; i += 8)
        s[ty + i][tx] = W[(by * 32 + ty + i) * DMODEL + bx * 32 + tx];
    __syncthreads();
#pragma unroll
    for (int i = 0; i < 32; i += 8) {
        float x = s[tx][ty + i];
        int n = bx * 32 + ty + i;
        int k = by * 32 + tx;
        __nv_bfloat16 h = __float2bfloat16(x);
        Thi[n * DMODEL + k] = h;
        Tlo[n * DMODEL + k] = __float2bfloat16(x - __bfloat162float(h));
    }
}

// ---------------------------------------------------------------------------
// fp32 SGEMM with packed f32x2 FMA; conflict-free B fragments.
// Thread (tx,ty) owns rows ty*8+i and column PAIRS (2tx+32j, 2tx+32j+1),
// j=0..3: B fragment = 4x LDS.64 hitting all 32 banks exactly once.
// gridDim.z selects Q or K projection (one launch for both).
// ---------------------------------------------------------------------------
__global__ void __launch_bounds__(256, 2)
sgemm_bias_x2_qk(const float* __restrict__ A0, const float* __restrict__ W0,
                 const float* __restrict__ bias0, float* __restrict__ C0,
                 const float* __restrict__ A1, const float* __restrict__ W1,
                 const float* __restrict__ bias1, float* __restrict__ C1)
{
    __shared__ float As[8][128];   // transposed A tile: As[k][m]
    __shared__ float Bs[8][128];   // Bs[k][n]

    const float* A    = blockIdx.z ? A1 : A0;
    const float* W    = blockIdx.z ? W1 : W0;
    const float* bias = blockIdx.z ? bias1 : bias0;
    float*       C    = blockIdx.z ? C1 : C0;

    const int tid = threadIdx.x;
    const int bm = blockIdx.y * 128;
    const int bn = blockIdx.x * 128;
    const int tx = tid & 15;
    const int ty = tid >> 4;

    const int arow = tid >> 1;
    const int ac4  = (tid & 1) << 2;
    const int brow = tid >> 5;
    const int bc4  = (tid & 31) << 2;

    const float* Ap = A + (size_t)(bm + arow) * DMODEL + ac4;
    const float* Wp = W + (size_t)brow * DMODEL + (bn + bc4);

    unsigned long long acc2[8][4];
#pragma unroll
    for (int i = 0; i < 8; i++)
#pragma unroll
        for (int j = 0; j < 4; j++) acc2[i][j] = 0ull;

    for (int k0 = 0; k0 < DMODEL; k0 += 8) {
        const float4 av = *(const float4*)(Ap + k0);
        const float4 bv = *(const float4*)(Wp + (size_t)k0 * DMODEL);
        __syncthreads();
        As[ac4 + 0][arow] = av.x;
        As[ac4 + 1][arow] = av.y;
        As[ac4 + 2][arow] = av.z;
        As[ac4 + 3][arow] = av.w;
        *(float4*)&Bs[brow][bc4] = bv;
        __syncthreads();

#pragma unroll
        for (int k = 0; k < 8; k++) {
            float a[8];
            *(float4*)&a[0] = *(const float4*)&As[k][ty * 8];
            *(float4*)&a[4] = *(const float4*)&As[k][ty * 8 + 4];
            unsigned long long b2[4];
#pragma unroll
            for (int j = 0; j < 4; j++)
                b2[j] = *(const unsigned long long*)&Bs[k][2 * tx + 32 * j];
            unsigned long long a2[8];
#pragma unroll
            for (int i = 0; i < 8; i++) SPLAT2(a2[i], __float_as_uint(a[i]));
#pragma unroll
            for (int i = 0; i < 8; i++)
#pragma unroll
                for (int j = 0; j < 4; j++)
                    FMA2(acc2[i][j], a2[i], b2[j]);
        }
    }

#pragma unroll
    for (int i = 0; i < 8; i++) {
        float* crow = C + (size_t)(bm + ty * 8 + i) * DMODEL + bn;
#pragma unroll
        for (int j = 0; j < 4; j++) {
            const int col = 2 * tx + 32 * j;
            unsigned lo, hi;
            UNPK2(lo, hi, acc2[i][j]);
            float2 o;
            o.x = __uint_as_float(lo) + bias[bn + col];
            o.y = __uint_as_float(hi) + bias[bn + col + 1];
            *(float2*)(crow + col) = o;
        }
    }
}

// ---------------------------------------------------------------------------
// Tensor-core GEMM (bf16 3-MMA split) — V and output projections.
// ---------------------------------------------------------------------------
#define GBM 128
#define GBN 128
#define GBK 32
#define GSTR 40
#define GSTAGE 20480
#define GNK (DMODEL / GBK)

#define MMA16816(c, a, b0, b1)                                               \
    asm volatile(                                                            \
        "mma.sync.aligned.m16n8k16.row.col.f32.bf16.bf16.f32 "               \
        "{%0,%1,%2,%3},{%4,%5,%6,%7},{%8,%9},{%0,%1,%2,%3};"                 \
        : "+f"(c[0]), "+f"(c[1]), "+f"(c[2]), "+f"(c[3])                     \
        : "r"(a[0]), "r"(a[1]), "r"(a[2]), "r"(a[3]), "r"(b0), "r"(b1))

#define CPA16(sdst, gsrc)                                                    \
    {                                                                        \
        uint32_t _d = (uint32_t)__cvta_generic_to_shared(sdst);              \
        asm volatile("cp.async.cg.shared.global [%0], [%1], 16;"             \
                     :: "r"(_d), "l"(gsrc));                                 \
    }

__global__ void __launch_bounds__(256, 2)
gemm_bf16x3(const __nv_bfloat16* __restrict__ Ahi,
            const __nv_bfloat16* __restrict__ Alo,
            const __nv_bfloat16* __restrict__ Bthi,
            const __nv_bfloat16* __restrict__ Btlo,
            const float* __restrict__ bias, float* __restrict__ C)
{
    extern __shared__ __nv_bfloat16 sm[];
    const int tid = threadIdx.x;
    const int lane = tid & 31;
    const int g = lane >> 2;
    const int tg = lane & 3;
    const int wid = tid >> 5;
    const int warp_m = wid >> 1;
    const int warp_n = wid & 1;
    const int bm = blockIdx.y * GBM;
    const int bn = blockIdx.x * GBN;

    float acc[2][8][4];
#pragma unroll
    for (int mt = 0; mt < 2; mt++)
#pragma unroll
        for (int nt = 0; nt < 8; nt++)
#pragma unroll
            for (int j = 0; j < 4; j++) acc[mt][nt][j] = 0.0f;

    const int ld_row = tid >> 2;
    const int ld_q   = tid & 3;

    const __nv_bfloat16* gAh = Ahi + (size_t)bm * DMODEL;
    const __nv_bfloat16* gAl = Alo + (size_t)bm * DMODEL;
    const __nv_bfloat16* gBh = Bthi + (size_t)bn * DMODEL;
    const __nv_bfloat16* gBl = Btlo + (size_t)bn * DMODEL;

    auto issue_stage = [&](int kt) {
        const int k0 = kt * GBK;
        __nv_bfloat16* base = sm + (kt & 1) * GSTAGE;
#pragma unroll
        for (int cc = 0; cc < 2; cc++) {
            const int row = ld_row + cc * 64;
            const int soff = row * GSTR + ld_q * 8;
            const size_t goff = (size_t)row * DMODEL + k0 + ld_q * 8;
            CPA16(base + soff,         gAh + goff);
            CPA16(base + 5120 + soff,  gAl + goff);
            CPA16(base + 10240 + soff, gBh + goff);
            CPA16(base + 15360 + soff, gBl + goff);
        }
        asm volatile("cp.async.commit_group;");
    };

    issue_stage(0);

    for (int kt = 0; kt < GNK; kt++) {
        asm volatile("cp.async.wait_group 0;" ::: "memory");
        __syncthreads();
        if (kt + 1 < GNK) issue_stage(kt + 1);

        const __nv_bfloat16* sa_hi = sm + (kt & 1) * GSTAGE;
        const __nv_bfloat16* sa_lo = sa_hi + 5120;
        const __nv_bfloat16* sb_hi = sa_hi + 10240;
        const __nv_bfloat16* sb_lo = sa_hi + 15360;

#pragma unroll
        for (int ks = 0; ks < 2; ks++) {
            const int kb = ks * 16 + tg * 2;
            uint32_t ah[2][4], al[2][4];
#pragma unroll
            for (int mt = 0; mt < 2; mt++) {
                const int r = warp_m * 32 + mt * 16 + g;
                const __nv_bfloat16* pa = sa_hi + r * GSTR + kb;
                ah[mt][0] = *(const uint32_t*)(pa);
                ah[mt][1] = *(const uint32_t*)(pa + 8 * GSTR);
                ah[mt][2] = *(const uint32_t*)(pa + 8);
                ah[mt][3] = *(const uint32_t*)(pa + 8 * GSTR + 8);
                const __nv_bfloat16* pl = sa_lo + r * GSTR + kb;
                al[mt][0] = *(const uint32_t*)(pl);
                al[mt][1] = *(const uint32_t*)(pl + 8 * GSTR);
                al[mt][2] = *(const uint32_t*)(pl + 8);
                al[mt][3] = *(const uint32_t*)(pl + 8 * GSTR + 8);
            }
#pragma unroll
            for (int nt = 0; nt < 8; nt++) {
                const int n = warp_n * 64 + nt * 8 + g;
                const __nv_bfloat16* pb = sb_hi + n * GSTR + kb;
                uint32_t bh0 = *(const uint32_t*)(pb);
                uint32_t bh1 = *(const uint32_t*)(pb + 8);
                const __nv_bfloat16* pbl = sb_lo + n * GSTR + kb;
                uint32_t bl0 = *(const uint32_t*)(pbl);
                uint32_t bl1 = *(const uint32_t*)(pbl + 8);
#pragma unroll
                for (int mt = 0; mt < 2; mt++) {
                    MMA16816(acc[mt][nt], ah[mt], bh0, bh1);
                    MMA16816(acc[mt][nt], ah[mt], bl0, bl1);
                    MMA16816(acc[mt][nt], al[mt], bh0, bh1);
                }
            }
        }
    }

#pragma unroll
    for (int mt = 0; mt < 2; mt++) {
        const int r0 = bm + warp_m * 32 + mt * 16 + g;
#pragma unroll
        for (int nt = 0; nt < 8; nt++) {
            const int col = bn + warp_n * 64 + nt * 8 + tg * 2;
            const float bx = bias[col];
            const float by = bias[col + 1];
            float2 v0 = make_float2(acc[mt][nt][0] + bx, acc[mt][nt][1] + by);
            float2 v1 = make_float2(acc[mt][nt][2] + bx, acc[mt][nt][3] + by);
            *(float2*)&C[(size_t)r0 * DMODEL + col] = v0;
            *(float2*)&C[(size_t)(r0 + 8) * DMODEL + col] = v1;
        }
    }
}

// ---------------------------------------------------------------------------
// Sparse causal attention with top-k renormalization.
// f32x2 packed score accumulation; bitmask top-k extraction (no tmp[16]
// copy -> fewer regs); 3 CTAs/SM for occupancy; coalesced fp32 output.
// ---------------------------------------------------------------------------
#define AT_ROWS 16
#define KTILE   128
#define KPAD    (KTILE + 4)
#define CAP     32
#define NEGINF  (-CUDART_INF_F)

__global__ void __launch_bounds__(256, 3)
attn_sparse(const float* __restrict__ Q, const float* __restrict__ K,
            const float* __restrict__ V, const int* __restrict__ kidx_p,
            float* __restrict__ O)
{
    __shared__ float ks[DKH][KPAD];        // transposed K tile
    __shared__ float qs[AT_ROWS][DKH];
    __shared__ float lw[AT_ROWS][CAP];
    __shared__ int   lj[AT_ROWS][CAP];
    __shared__ int   lcnt[AT_ROWS];

    const int bh = blockIdx.y;
    const int b  = bh >> 3;
    const int h  = bh & 7;
    const int row_base = blockIdx.x * AT_ROWS;
    const int tid  = threadIdx.x;
    const int wid  = tid >> 5;
    const int lane = tid & 31;
    const int kk   = *kidx_p;

    const size_t base = ((size_t)b * SEQ) * DMODEL + (size_t)h * DKH;

    for (int i = tid; i < AT_ROWS * DKH; i += 256) {
        int rr = i >> 6, d = i & 63;
        qs[rr][d] = Q[base + (size_t)(row_base + rr) * DMODEL + d];
    }

    const int nkeys = row_base + AT_ROWS - 1;   // strictly-causal: keys j < r
    const int lr0 = wid * 2;

    unsigned long long sc2[2][8];
#pragma unroll
    for (int p = 0; p < 8; p++) { sc2[0][p] = 0ull; sc2[1][p] = 0ull; }

    // ---- score pass: QK^T over key tiles ----
#pragma unroll
    for (int tt = 0; tt < 4; tt++) {
        const int t0 = tt << 7;
        if (t0 >= nkeys) break;
        const int tl = min(KTILE, nkeys - t0);
        __syncthreads();
        for (int i = tid; i < KTILE * 16; i += 256) {
            const int key = i >> 4;
            const int d4  = (i & 15) << 2;
            float4 kv;
            if (key < tl)
                kv = *(const float4*)&K[base + (size_t)(t0 + key) * DMODEL + d4];
            else
                kv = make_float4(0.f, 0.f, 0.f, 0.f);
            ks[d4 + 0][key] = kv.x;
            ks[d4 + 1][key] = kv.y;
            ks[d4 + 2][key] = kv.z;
            ks[d4 + 3][key] = kv.w;
        }
        __syncthreads();
#pragma unroll 4
        for (int d4 = 0; d4 < DKH; d4 += 4) {
            const float4 qa4 = *(const float4*)&qs[lr0][d4];
            const float4 qb4 = *(const float4*)&qs[lr0 + 1][d4];
#pragma unroll
            for (int dd = 0; dd < 4; dd++) {
                const ulonglong2 kv2 =
                    *(const ulonglong2*)&ks[d4 + dd][lane << 2];
                unsigned long long qa2, qb2;
                SPLAT2(qa2, __float_as_uint((&qa4.x)[dd]));
                SPLAT2(qb2, __float_as_uint((&qb4.x)[dd]));
                FMA2(sc2[0][tt * 2 + 0], qa2, kv2.x);
                FMA2(sc2[0][tt * 2 + 1], qa2, kv2.y);
                FMA2(sc2[1][tt * 2 + 0], qb2, kv2.x);
                FMA2(sc2[1][tt * 2 + 1], qb2, kv2.y);
            }
        }
    }

    // unpack packed accumulators into scalar score slots
    float sc[2][16];
#pragma unroll
    for (int rr = 0; rr < 2; rr++)
#pragma unroll
        for (int p = 0; p < 8; p++) {
            unsigned lo, hi;
            UNPK2(lo, hi, sc2[rr][p]);
            sc[rr][p * 2]     = __uint_as_float(lo);
            sc[rr][p * 2 + 1] = __uint_as_float(hi);
        }

    // ---- mask invalid keys & apply 1/sqrt(DK) ----
#pragma unroll
    for (int rr = 0; rr < 2; rr++) {
        const int r = row_base + lr0 + rr;
#pragma unroll
        for (int s = 0; s < 16; s++) {
            const int j = ((s >> 2) << 7) + (lane << 2) + (s & 3);
            sc[rr][s] = (j < r) ? sc[rr][s] * 0.125f : NEGINF;
        }
    }

    // ---- per-row: top-k threshold, weights, sparse PV ----
#pragma unroll
    for (int rr = 0; rr < 2; rr++) {
        const int r  = row_base + lr0 + rr;
        const int lr = lr0 + rr;
        float o0 = 0.0f, o1 = 0.0f;

        if (r > 0) {
            unsigned removed = 0;   // bitmask of extracted slots (no tmp copy)
            const int nex = (r >= kk) ? kk : 1;
            float m = 0.0f, t = NEGINF;
            for (int e = 0; e < nex; e++) {
                float lm = NEGINF;
#pragma unroll
                for (int s = 0; s < 16; s++) {
                    const float vv =
                        (removed & (1u << s)) ? NEGINF : sc[rr][s];
                    lm = fmaxf(lm, vv);
                }
                float wm = lm;
#pragma unroll
                for (int off = 16; off > 0; off >>= 1)
                    wm = fmaxf(wm, __shfl_xor_sync(0xffffffffu, wm, off));
                if (e == 0) m = wm;
                t = wm;
                const unsigned ball = __ballot_sync(0xffffffffu, lm == wm);
                const int owner = __ffs(ball) - 1;
                if (lane == owner) {
                    bool rm = false;
#pragma unroll
                    for (int s = 0; s < 16; s++) {
                        if (!rm && !(removed & (1u << s)) && sc[rr][s] == wm) {
                            removed |= (1u << s);
                            rm = true;
                        }
                    }
                }
            }
            if (r < kk) t = -3.0e38f;   // dense softmax path: keep all valid

            float ksum = 0.0f;
#pragma unroll
            for (int s = 0; s < 16; s++)
                if (sc[rr][s] >= t) ksum += __expf(sc[rr][s] - m);
#pragma unroll
            for (int off = 16; off > 0; off >>= 1)
                ksum += __shfl_xor_sync(0xffffffffu, ksum, off);
            const float inv = 1.0f / ksum;

            if (lane == 0) lcnt[lr] = 0;
            __syncwarp();
#pragma unroll
            for (int s = 0; s < 16; s++) {
                if (sc[rr][s] >= t) {
                    const int p = atomicAdd(&lcnt[lr], 1);
                    if (p < CAP) {
                        lw[lr][p] = __expf(sc[rr][s] - m) * inv;
                        lj[lr][p] = ((s >> 2) << 7) + (lane << 2) + (s & 3);
                    }
                }
            }
            __syncwarp();
            const int cnt = min(lcnt[lr], CAP);
            for (int e = 0; e < cnt; e++) {
                const float w = lw[lr][e];
                const int   j = lj[lr][e];
                const float* vrow = &V[base + (size_t)j * DMODEL];
                o0 = fmaf(w, vrow[lane], o0);
                o1 = fmaf(w, vrow[lane + 32], o1);
            }
            __syncwarp();
        }
        O[base + (size_t)r * DMODEL + lane]      = o0;
        O[base + (size_t)r * DMODEL + lane + 32] = o1;
    }
}

// ---------------------------------------------------------------------------
extern "C" void kernel_launch(void* const* d_in, const int* in_sizes, int n_in,
                              void* d_out, int out_size)
{
    const float* q   = (const float*)d_in[0];
    const float* k   = (const float*)d_in[1];
    const float* v   = (const float*)d_in[2];
    const float* w_q = (const float*)d_in[3];
    const float* b_q = (const float*)d_in[4];
    const float* w_k = (const float*)d_in[5];
    const float* b_k = (const float*)d_in[6];
    const float* w_v = (const float*)d_in[7];
    const float* b_v = (const float*)d_in[8];
    const float* w_o = (const float*)d_in[9];
    const float* b_o = (const float*)d_in[10];
    const int*   kid = (const int*)d_in[11];
    float* out = (float*)d_out;

    float *Qp, *Kp, *Vp, *AO;
    __nv_bfloat16 *Ahi, *Alo, *Wthi, *Wtlo;
    cudaGetSymbolAddress((void**)&Qp, g_Qp);
    cudaGetSymbolAddress((void**)&Kp, g_Kp);
    cudaGetSymbolAddress((void**)&Vp, g_Vp);
    cudaGetSymbolAddress((void**)&AO, g_AO);
    cudaGetSymbolAddress((void**)&Ahi, g_Ahi);
    cudaGetSymbolAddress((void**)&Alo, g_Alo);
    cudaGetSymbolAddress((void**)&Wthi, g_Wthi);
    cudaGetSymbolAddress((void**)&Wtlo, g_Wtlo);

    cudaFuncSetAttribute(gemm_bf16x3,
                         cudaFuncAttributeMaxDynamicSharedMemorySize,
                         2 * GSTAGE * (int)sizeof(__nv_bfloat16));

    const int n4 = MROWS * DMODEL / 4;
    const int cblk = (n4 + 255) / 256;
    dim3 tgrid(16, 16), tblk(32, 8);
    dim3 ggrid(DMODEL / GBN, MROWS / GBM);        // (4, 128)
    dim3 ggrid_qk(DMODEL / 128, MROWS / 128, 2);  // Q and K in one launch
    const int smem = 2 * GSTAGE * (int)sizeof(__nv_bfloat16);

    // V projection path first (independent of Q/K).
    convT<<<tgrid, tblk>>>(w_v, Wthi, Wtlo);
    convA<<<cblk, 256>>>((const float4*)v, (uint2*)Ahi, (uint2*)Alo, n4);
    gemm_bf16x3<<<ggrid, 256, smem>>>(Ahi, Alo, Wthi, Wtlo, b_v, Vp);

    // Q + K projections: exact fp32 (packed f32x2 FMA), one launch.
    sgemm_bias_x2_qk<<<ggrid_qk, 256>>>(q, w_q, b_q, Qp, k, w_k, b_k, Kp);

    // Pre-split output-projection weights (independent of attn).
    convT<<<tgrid, tblk>>>(w_o, Wthi, Wtlo);

    // Attention — coalesced fp32 output.
    dim3 ga(SEQ / AT_ROWS, BATCH * HEADS); // (32, 256)
    attn_sparse<<<ga, 256>>>(Qp, Kp, Vp, kid, AO);

    // Split attn output, then output projection.
    convA<<<cblk, 256>>>((const float4*)AO, (uint2*)Ahi, (uint2*)Alo, n4);
    gemm_bf16x3<<<ggrid, 256, smem>>>(Ahi, Alo, Wthi, Wtlo, b_o, out);
}